// round 1
// baseline (speedup 1.0000x reference)
#include <cuda_runtime.h>
#include <math.h>

// ---------------- problem constants ----------------
#define BATCH 256
// conv1: in [B,3,250,250], w [6,3,5,5], s=2, p=1 -> [B,6,124,124]
#define C1_IC 3
#define C1_OC 6
#define C1_IH 250
#define C1_OH 124
// pool1 (k2,s1) -> [B,6,123,123]
#define P1_OH 123
// conv2: w [15,6,3,3], s=2, p=1 -> [B,15,62,62]
#define C2_IC 6
#define C2_OC 15
#define C2_OH 62
// pool2 -> [B,15,61,61]
#define P2_OH 61
#define FC1_IN 55815   // 15*61*61
#define FC1_OUT 120
#define FC2_OUT 84

#define KSPLIT 32
#define KCHUNK 1760    // 55*32, KSPLIT*KCHUNK = 56320 >= 55815
#define KT 32

// ---------------- device scratch (no allocations allowed) ----------------
__device__ float g_c1[BATCH * C1_OC * C1_OH * C1_OH];     // 94.5 MB
__device__ float g_p1[BATCH * C1_OC * P1_OH * P1_OH];     // 93 MB
__device__ float g_c2[BATCH * C2_OC * C2_OH * C2_OH];     // 59 MB
__device__ float g_p2[BATCH * C2_OC * P2_OH * P2_OH];     // 57 MB (= fc1 input, flattened)
__device__ float g_fc1p[KSPLIT * BATCH * FC1_OUT];        // 3.9 MB partials
__device__ float g_h1[BATCH * FC1_OUT];
__device__ float g_feat[BATCH * FC2_OUT];
__device__ float g_probs[BATCH];
__device__ float g_norms[BATCH];

// ---------------- conv1 + bias + relu ----------------
__global__ void conv1_kernel(const float* __restrict__ x,
                             const float* __restrict__ w,
                             const float* __restrict__ bias) {
    __shared__ float sw[C1_OC * C1_IC * 25];   // 450
    int t = threadIdx.y * 16 + threadIdx.x;
    for (int i = t; i < C1_OC * C1_IC * 25; i += 256) sw[i] = w[i];
    __syncthreads();

    int ox = blockIdx.x * 16 + threadIdx.x;
    int oy = blockIdx.y * 16 + threadIdx.y;
    int b  = blockIdx.z;
    if (ox >= C1_OH || oy >= C1_OH) return;

    float acc[C1_OC];
#pragma unroll
    for (int oc = 0; oc < C1_OC; oc++) acc[oc] = bias[oc];

#pragma unroll
    for (int ic = 0; ic < C1_IC; ic++) {
        const float* xin = x + ((long)b * C1_IC + ic) * C1_IH * C1_IH;
#pragma unroll
        for (int ky = 0; ky < 5; ky++) {
            int iy = oy * 2 - 1 + ky;
            if (iy < 0 || iy >= C1_IH) continue;
#pragma unroll
            for (int kx = 0; kx < 5; kx++) {
                int ix = ox * 2 - 1 + kx;
                if (ix < 0 || ix >= C1_IH) continue;
                float v = xin[iy * C1_IH + ix];
#pragma unroll
                for (int oc = 0; oc < C1_OC; oc++)
                    acc[oc] = fmaf(v, sw[(oc * C1_IC + ic) * 25 + ky * 5 + kx], acc[oc]);
            }
        }
    }
#pragma unroll
    for (int oc = 0; oc < C1_OC; oc++)
        g_c1[(((long)b * C1_OC + oc) * C1_OH + oy) * C1_OH + ox] = fmaxf(acc[oc], 0.f);
}

// ---------------- generic 2x2 stride-1 maxpool ----------------
__global__ void pool_kernel(const float* __restrict__ in, float* __restrict__ out,
                            int C, int IH, int OH, long total) {
    long idx = (long)blockIdx.x * blockDim.x + threadIdx.x;
    if (idx >= total) return;
    int ox = idx % OH;
    int oy = (idx / OH) % OH;
    long bc = idx / ((long)OH * OH);   // b*C + c
    const float* p = in + bc * IH * IH + (long)oy * IH + ox;
    float m = fmaxf(fmaxf(p[0], p[1]), fmaxf(p[IH], p[IH + 1]));
    out[idx] = m;
}

// ---------------- conv2 + bias + relu ----------------
__global__ void conv2_kernel(const float* __restrict__ w,
                             const float* __restrict__ bias) {
    __shared__ float sw[C2_OC * C2_IC * 9];    // 810
    int t = threadIdx.y * 16 + threadIdx.x;
    for (int i = t; i < C2_OC * C2_IC * 9; i += 256) sw[i] = w[i];
    __syncthreads();

    int ox = blockIdx.x * 16 + threadIdx.x;
    int oy = blockIdx.y * 16 + threadIdx.y;
    int b  = blockIdx.z;
    if (ox >= C2_OH || oy >= C2_OH) return;

    float acc[C2_OC];
#pragma unroll
    for (int oc = 0; oc < C2_OC; oc++) acc[oc] = bias[oc];

#pragma unroll
    for (int ic = 0; ic < C2_IC; ic++) {
        const float* xin = g_p1 + ((long)b * C2_IC + ic) * P1_OH * P1_OH;
#pragma unroll
        for (int ky = 0; ky < 3; ky++) {
            int iy = oy * 2 - 1 + ky;
            if (iy < 0 || iy >= P1_OH) continue;
#pragma unroll
            for (int kx = 0; kx < 3; kx++) {
                int ix = ox * 2 - 1 + kx;
                if (ix < 0 || ix >= P1_OH) continue;
                float v = xin[iy * P1_OH + ix];
#pragma unroll
                for (int oc = 0; oc < C2_OC; oc++)
                    acc[oc] = fmaf(v, sw[(oc * C2_IC + ic) * 9 + ky * 3 + kx], acc[oc]);
            }
        }
    }
#pragma unroll
    for (int oc = 0; oc < C2_OC; oc++)
        g_c2[(((long)b * C2_OC + oc) * C2_OH + oy) * C2_OH + ox] = fmaxf(acc[oc], 0.f);
}

// ---------------- fc1: [256,55815] @ [120,55815]^T, K-split tiled GEMM ----------------
// grid (Mtiles=4, KSPLIT), block 256 threads. Tile: 64 rows x 128 cols (120 valid).
__global__ void fc1_kernel(const float* __restrict__ wfc) {
    __shared__ float As[64][KT + 1];
    __shared__ float Bs[128][KT + 1];

    int mtile = blockIdx.x;
    int kb    = blockIdx.y;
    int m0    = mtile * 64;
    int kbeg  = kb * KCHUNK;
    int kend  = min(kbeg + KCHUNK, FC1_IN);

    int tx = threadIdx.x & 15;
    int ty = threadIdx.x >> 4;

    float acc[4][8];
#pragma unroll
    for (int i = 0; i < 4; i++)
#pragma unroll
        for (int j = 0; j < 8; j++) acc[i][j] = 0.f;

    for (int k0 = kbeg; k0 < kend; k0 += KT) {
        int kt = min(KT, kend - k0);
        for (int i = threadIdx.x; i < 64 * KT; i += 256) {
            int r = i / KT, c = i % KT;
            As[r][c] = (c < kt) ? g_p2[(long)(m0 + r) * FC1_IN + k0 + c] : 0.f;
        }
        for (int i = threadIdx.x; i < 128 * KT; i += 256) {
            int r = i / KT, c = i % KT;
            Bs[r][c] = (r < FC1_OUT && c < kt) ? wfc[(long)r * FC1_IN + k0 + c] : 0.f;
        }
        __syncthreads();
#pragma unroll
        for (int kk = 0; kk < KT; kk++) {
            float a[4], bb[8];
#pragma unroll
            for (int i = 0; i < 4; i++) a[i] = As[ty + 16 * i][kk];
#pragma unroll
            for (int j = 0; j < 8; j++) bb[j] = Bs[tx + 16 * j][kk];
#pragma unroll
            for (int i = 0; i < 4; i++)
#pragma unroll
                for (int j = 0; j < 8; j++) acc[i][j] = fmaf(a[i], bb[j], acc[i][j]);
        }
        __syncthreads();
    }
#pragma unroll
    for (int i = 0; i < 4; i++) {
        int m = m0 + ty + 16 * i;
#pragma unroll
        for (int j = 0; j < 8; j++) {
            int n = tx + 16 * j;
            if (n < FC1_OUT)
                g_fc1p[((long)kb * BATCH + m) * FC1_OUT + n] = acc[i][j];
        }
    }
}

// ---------------- fc1 reduce + bias + relu ----------------
__global__ void fc1_reduce_kernel(const float* __restrict__ bias) {
    int idx = blockIdx.x * blockDim.x + threadIdx.x;
    if (idx >= BATCH * FC1_OUT) return;
    int n = idx % FC1_OUT;
    float s = bias[n];
#pragma unroll
    for (int kb = 0; kb < KSPLIT; kb++)
        s += g_fc1p[(long)kb * BATCH * FC1_OUT + idx];
    g_h1[idx] = fmaxf(s, 0.f);
}

// ---------------- fc2: features = h1 @ fc2_w^T + b  (no relu) ----------------
__global__ void fc2_kernel(const float* __restrict__ w, const float* __restrict__ bias) {
    int b = blockIdx.x;
    __shared__ float h[FC1_OUT];
    if (threadIdx.x < FC1_OUT) h[threadIdx.x] = g_h1[b * FC1_OUT + threadIdx.x];
    __syncthreads();
    int n = threadIdx.x;
    if (n < FC2_OUT) {
        float s = bias[n];
        const float* wr = w + n * FC1_OUT;
#pragma unroll 8
        for (int k = 0; k < FC1_OUT; k++) s = fmaf(h[k], wr[k], s);
        g_feat[b * FC2_OUT + n] = s;
    }
}

// ---------------- head: fc3 -> tanh-param layer -> sigmoid; also feature norms ----------------
__global__ void head_kernel(const float* __restrict__ fc3w, const float* __restrict__ fc3b,
                            const float* __restrict__ plw, const float* __restrict__ plb,
                            const float* __restrict__ pls, const float* __restrict__ plbias) {
    int b = threadIdx.x;  // 256 threads
    float s = fc3b[0];
    float nrm = 0.f;
#pragma unroll 4
    for (int k = 0; k < FC2_OUT; k++) {
        float f = g_feat[b * FC2_OUT + k];
        s = fmaf(f, fc3w[k], s);
        nrm = fmaf(f, f, nrm);
    }
    g_norms[b] = sqrtf(nrm);
    float z = tanhf(s * plw[0] + plb[0]) * pls[0] + plbias[0];
    g_probs[b] = 1.f / (1.f + expf(-z));
}

// ---------------- graph aggregation: cosine-sim adjacency, degree-weighted mean ----------------
__global__ void graph_kernel(float* __restrict__ out) {
    int i = blockIdx.x;
    int j = threadIdx.x;
    __shared__ float fi[FC2_OUT];
    __shared__ float sdeg[256];
    __shared__ float ssum[256];
    if (j < FC2_OUT) fi[j] = g_feat[i * FC2_OUT + j];
    __syncthreads();

    float dot = 0.f;
#pragma unroll 4
    for (int k = 0; k < FC2_OUT; k++) dot = fmaf(fi[k], g_feat[j * FC2_OUT + k], dot);
    float sim = dot / (g_norms[i] * g_norms[j] + 1e-12f);
    float a = (sim >= 0.f && i != j) ? 1.f : 0.f;

    sdeg[j] = a;
    ssum[j] = a * g_probs[j];
    __syncthreads();
    for (int s = 128; s > 0; s >>= 1) {
        if (j < s) { sdeg[j] += sdeg[j + s]; ssum[j] += ssum[j + s]; }
        __syncthreads();
    }
    if (j == 0) {
        float deg = sdeg[0];
        float nm  = (deg > 0.f) ? (ssum[0] / fmaxf(deg, 1.f)) : 0.f;
        float agg = (g_probs[i] + nm) / (1.f + deg);
        out[i * 2 + 0] = agg;
        out[i * 2 + 1] = 1.f - agg;
    }
}

// ---------------- launch ----------------
extern "C" void kernel_launch(void* const* d_in, const int* in_sizes, int n_in,
                              void* d_out, int out_size) {
    const float* x       = (const float*)d_in[0];
    const float* conv1_w = (const float*)d_in[1];
    const float* conv1_b = (const float*)d_in[2];
    const float* conv2_w = (const float*)d_in[3];
    const float* conv2_b = (const float*)d_in[4];
    const float* fc1_w   = (const float*)d_in[5];
    const float* fc1_b   = (const float*)d_in[6];
    const float* fc2_w   = (const float*)d_in[7];
    const float* fc2_b   = (const float*)d_in[8];
    const float* fc3_w   = (const float*)d_in[9];
    const float* fc3_b   = (const float*)d_in[10];
    const float* pl_w    = (const float*)d_in[11];
    const float* pl_b    = (const float*)d_in[12];
    const float* pl_s    = (const float*)d_in[13];
    const float* pl_bias = (const float*)d_in[14];
    float* out = (float*)d_out;

    // conv1 + relu
    {
        dim3 blk(16, 16), grd((C1_OH + 15) / 16, (C1_OH + 15) / 16, BATCH);
        conv1_kernel<<<grd, blk>>>(x, conv1_w, conv1_b);
    }
    // pool1
    {
        float* dc1; cudaGetSymbolAddress((void**)&dc1, g_c1);
        float* dp1; cudaGetSymbolAddress((void**)&dp1, g_p1);
        long total = (long)BATCH * C1_OC * P1_OH * P1_OH;
        pool_kernel<<<(unsigned)((total + 255) / 256), 256>>>(dc1, dp1, C1_OC, C1_OH, P1_OH, total);
    }
    // conv2 + relu
    {
        dim3 blk(16, 16), grd((C2_OH + 15) / 16, (C2_OH + 15) / 16, BATCH);
        conv2_kernel<<<grd, blk>>>(conv2_w, conv2_b);
    }
    // pool2
    {
        float* dc2; cudaGetSymbolAddress((void**)&dc2, g_c2);
        float* dp2; cudaGetSymbolAddress((void**)&dp2, g_p2);
        long total = (long)BATCH * C2_OC * P2_OH * P2_OH;
        pool_kernel<<<(unsigned)((total + 255) / 256), 256>>>(dc2, dp2, C2_OC, C2_OH, P2_OH, total);
    }
    // fc1 (K-split GEMM) + reduce
    {
        dim3 grd(4, KSPLIT);
        fc1_kernel<<<grd, 256>>>(fc1_w);
        fc1_reduce_kernel<<<(BATCH * FC1_OUT + 255) / 256, 256>>>(fc1_b);
    }
    // fc2
    fc2_kernel<<<BATCH, 128>>>(fc2_w, fc2_b);
    // head (probs + norms)
    head_kernel<<<1, BATCH>>>(fc3_w, fc3_b, pl_w, pl_b, pl_s, pl_bias);
    // graph aggregation -> output [256,2]
    graph_kernel<<<BATCH, BATCH>>>(out);
}

// round 2
// speedup vs baseline: 1.2286x; 1.2286x over previous
#include <cuda_runtime.h>
#include <math.h>

// ---------------- problem constants ----------------
#define BATCH 256
#define C1_IC 3
#define C1_OC 6
#define C1_IH 250
#define C1_OH 124
#define P1_OH 123
#define C2_IC 6
#define C2_OC 15
#define C2_OH 62
#define P2_OH 61
#define FC1_IN 55815   // 15*61*61
#define FC1_OUT 120
#define FC2_OUT 84

// ---------------- device scratch ----------------
__device__ float g_p1[BATCH * C1_OC * P1_OH * P1_OH];     // 93 MB
__device__ float g_p2[BATCH * C2_OC * P2_OH * P2_OH];     // 57 MB (fc1 input)
__device__ float g_fc1p[64 * BATCH * FC1_OUT];            // K-split partials
__device__ float g_h1[BATCH * FC1_OUT];
__device__ float g_feat[BATCH * FC2_OUT];
__device__ float g_probs[BATCH];
__device__ float g_norms[BATCH];

// ================= conv1 (5x5,s2,p1) + relu + maxpool(2,s1), fused =================
// pooled tile 32x16 per block => conv tile 33x17 = 561 positions, 6 oc.
#define C1_TPX 32
#define C1_TPY 16
#define C1_CW 33
#define C1_CH 17
#define C1_NPOS (C1_CW * C1_CH)          // 561
#define C1_XW 69                          // (33-1)*2+5
#define C1_XH 37                          // (17-1)*2+5
#define C1_THREADS 192

__global__ __launch_bounds__(C1_THREADS)
void conv1_pool_kernel(const float* __restrict__ x,
                       const float* __restrict__ w,
                       const float* __restrict__ bias) {
    __shared__ float xs[C1_IC][C1_XH * C1_XW];   // 30.6 KB
    __shared__ float cbuf[C1_OC][C1_NPOS];        // 13.5 KB
    __shared__ float sw[C1_OC * C1_IC * 25];      // 1.8 KB
    __shared__ float sb[C1_OC];

    const int tid = threadIdx.x;
    const int b   = blockIdx.z;
    const int px0 = blockIdx.x * C1_TPX;
    const int py0 = blockIdx.y * C1_TPY;
    const int ix0 = px0 * 2 - 1;
    const int iy0 = py0 * 2 - 1;

    for (int i = tid; i < C1_OC * C1_IC * 25; i += C1_THREADS) sw[i] = w[i];
    if (tid < C1_OC) sb[tid] = bias[tid];

    const float* xb = x + (long)b * C1_IC * C1_IH * C1_IH;
    for (int i = tid; i < C1_IC * C1_XH * C1_XW; i += C1_THREADS) {
        int ic = i / (C1_XH * C1_XW);
        int r  = (i / C1_XW) % C1_XH;
        int c  = i % C1_XW;
        int iy = iy0 + r, ix = ix0 + c;
        float v = 0.f;
        if (iy >= 0 && iy < C1_IH && ix >= 0 && ix < C1_IH)
            v = xb[ic * C1_IH * C1_IH + iy * C1_IH + ix];
        xs[ic][r * C1_XW + c] = v;
    }
    __syncthreads();

    // 3 positions per thread
    const int p0 = tid;
    const int p1 = tid + C1_THREADS;
    const int p2 = tid + 2 * C1_THREADS;
    const int p2c = (p2 < C1_NPOS) ? p2 : (C1_NPOS - 1);
    const int cy0 = p0 / C1_CW, cx0 = p0 % C1_CW;
    const int cy1 = p1 / C1_CW, cx1 = p1 % C1_CW;
    const int cy2 = p2c / C1_CW, cx2 = p2c % C1_CW;

    float a0[C1_OC], a1[C1_OC], a2[C1_OC];
#pragma unroll
    for (int oc = 0; oc < C1_OC; oc++) { a0[oc] = 0.f; a1[oc] = 0.f; a2[oc] = 0.f; }

#pragma unroll 1
    for (int ic = 0; ic < C1_IC; ic++) {
        const float* xp = xs[ic];
        const float* r0 = xp + (cy0 * 2) * C1_XW + cx0 * 2;
        const float* r1 = xp + (cy1 * 2) * C1_XW + cx1 * 2;
        const float* r2 = xp + (cy2 * 2) * C1_XW + cx2 * 2;
        const float* wp = sw + ic * 25;
#pragma unroll
        for (int ky = 0; ky < 5; ky++) {
#pragma unroll
            for (int kx = 0; kx < 5; kx++) {
                float x0 = r0[ky * C1_XW + kx];
                float x1 = r1[ky * C1_XW + kx];
                float x2 = r2[ky * C1_XW + kx];
#pragma unroll
                for (int oc = 0; oc < C1_OC; oc++) {
                    float wv = wp[oc * (C1_IC * 25) + ky * 5 + kx];
                    a0[oc] = fmaf(x0, wv, a0[oc]);
                    a1[oc] = fmaf(x1, wv, a1[oc]);
                    a2[oc] = fmaf(x2, wv, a2[oc]);
                }
            }
        }
    }
#pragma unroll
    for (int oc = 0; oc < C1_OC; oc++) {
        cbuf[oc][p0] = fmaxf(a0[oc] + sb[oc], 0.f);
        cbuf[oc][p1] = fmaxf(a1[oc] + sb[oc], 0.f);
        if (p2 < C1_NPOS) cbuf[oc][p2] = fmaxf(a2[oc] + sb[oc], 0.f);
    }
    __syncthreads();

    // pool 2x2 stride 1 and store
    for (int m = tid; m < C1_OC * C1_TPY * C1_TPX; m += C1_THREADS) {
        int oc  = m / (C1_TPY * C1_TPX);
        int rem = m % (C1_TPY * C1_TPX);
        int pyl = rem / C1_TPX, pxl = rem % C1_TPX;
        int px = px0 + pxl, py = py0 + pyl;
        if (px < P1_OH && py < P1_OH) {
            int q = pyl * C1_CW + pxl;
            float v = fmaxf(fmaxf(cbuf[oc][q], cbuf[oc][q + 1]),
                            fmaxf(cbuf[oc][q + C1_CW], cbuf[oc][q + C1_CW + 1]));
            g_p1[((long)(b * C1_OC + oc) * P1_OH + py) * P1_OH + px] = v;
        }
    }
}

// ================= conv2 (3x3,s2,p1) + relu + maxpool(2,s1), fused =================
// pooled tile 32x16 => conv tile 33x17 = 561 positions, 15 oc. Dynamic smem (~93KB).
#define C2_TPX 32
#define C2_TPY 16
#define C2_CW 33
#define C2_CH 17
#define C2_NPOS (C2_CW * C2_CH)          // 561
#define C2_XW 67                          // (33-1)*2+3
#define C2_XH 35                          // (17-1)*2+3
#define C2_THREADS 192
#define C2_XS_SZ (C2_IC * C2_XH * C2_XW)                 // 14070
#define C2_CB_SZ (C2_OC * C2_NPOS)                       // 8415
#define C2_SW_SZ (C2_OC * C2_IC * 9)                     // 810
#define C2_SMEM_BYTES ((C2_XS_SZ + C2_CB_SZ + C2_SW_SZ + C2_OC) * 4)

__global__ __launch_bounds__(C2_THREADS)
void conv2_pool_kernel(const float* __restrict__ w,
                       const float* __restrict__ bias) {
    extern __shared__ float smem[];
    float* xs   = smem;
    float* cbuf = xs + C2_XS_SZ;
    float* sw   = cbuf + C2_CB_SZ;
    float* sb   = sw + C2_SW_SZ;

    const int tid = threadIdx.x;
    const int b   = blockIdx.z;
    const int px0 = blockIdx.x * C2_TPX;
    const int py0 = blockIdx.y * C2_TPY;
    const int ix0 = px0 * 2 - 1;
    const int iy0 = py0 * 2 - 1;

    for (int i = tid; i < C2_SW_SZ; i += C2_THREADS) sw[i] = w[i];
    if (tid < C2_OC) sb[tid] = bias[tid];

    const float* xb = g_p1 + (long)b * C2_IC * P1_OH * P1_OH;
    for (int i = tid; i < C2_XS_SZ; i += C2_THREADS) {
        int ic = i / (C2_XH * C2_XW);
        int r  = (i / C2_XW) % C2_XH;
        int c  = i % C2_XW;
        int iy = iy0 + r, ix = ix0 + c;
        float v = 0.f;
        if (iy >= 0 && iy < P1_OH && ix >= 0 && ix < P1_OH)
            v = xb[ic * P1_OH * P1_OH + iy * P1_OH + ix];
        xs[ic * (C2_XH * C2_XW) + r * C2_XW + c] = v;
    }
    __syncthreads();

    const int p0 = tid;
    const int p1 = tid + C2_THREADS;
    const int p2 = tid + 2 * C2_THREADS;
    const int p2c = (p2 < C2_NPOS) ? p2 : (C2_NPOS - 1);
    const int cy0 = p0 / C2_CW, cx0 = p0 % C2_CW;
    const int cy1 = p1 / C2_CW, cx1 = p1 % C2_CW;
    const int cy2 = p2c / C2_CW, cx2 = p2c % C2_CW;

    float a0[C2_OC], a1[C2_OC], a2[C2_OC];
#pragma unroll
    for (int oc = 0; oc < C2_OC; oc++) { a0[oc] = 0.f; a1[oc] = 0.f; a2[oc] = 0.f; }

#pragma unroll 1
    for (int ic = 0; ic < C2_IC; ic++) {
        const float* xp = xs + ic * (C2_XH * C2_XW);
        const float* r0 = xp + (cy0 * 2) * C2_XW + cx0 * 2;
        const float* r1 = xp + (cy1 * 2) * C2_XW + cx1 * 2;
        const float* r2 = xp + (cy2 * 2) * C2_XW + cx2 * 2;
#pragma unroll
        for (int ky = 0; ky < 3; ky++) {
#pragma unroll
            for (int kx = 0; kx < 3; kx++) {
                float x0 = r0[ky * C2_XW + kx];
                float x1 = r1[ky * C2_XW + kx];
                float x2 = r2[ky * C2_XW + kx];
#pragma unroll
                for (int oc = 0; oc < C2_OC; oc++) {
                    float wv = sw[(oc * C2_IC + ic) * 9 + ky * 3 + kx];
                    a0[oc] = fmaf(x0, wv, a0[oc]);
                    a1[oc] = fmaf(x1, wv, a1[oc]);
                    a2[oc] = fmaf(x2, wv, a2[oc]);
                }
            }
        }
    }
#pragma unroll
    for (int oc = 0; oc < C2_OC; oc++) {
        cbuf[oc * C2_NPOS + p0] = fmaxf(a0[oc] + sb[oc], 0.f);
        cbuf[oc * C2_NPOS + p1] = fmaxf(a1[oc] + sb[oc], 0.f);
        if (p2 < C2_NPOS) cbuf[oc * C2_NPOS + p2] = fmaxf(a2[oc] + sb[oc], 0.f);
    }
    __syncthreads();

    for (int m = tid; m < C2_OC * C2_TPY * C2_TPX; m += C2_THREADS) {
        int oc  = m / (C2_TPY * C2_TPX);
        int rem = m % (C2_TPY * C2_TPX);
        int pyl = rem / C2_TPX, pxl = rem % C2_TPX;
        int px = px0 + pxl, py = py0 + pyl;
        if (px < P2_OH && py < P2_OH) {
            int q = pyl * C2_CW + pxl;
            const float* cb = cbuf + oc * C2_NPOS;
            float v = fmaxf(fmaxf(cb[q], cb[q + 1]),
                            fmaxf(cb[q + C2_CW], cb[q + C2_CW + 1]));
            g_p2[((long)(b * C2_OC + oc) * P2_OH + py) * P2_OH + px] = v;
        }
    }
}

// ================= fc1: [256,55815] @ [120,55815]^T, K-split GEMM =================
#define KSPLIT 64
#define KCHUNK 880   // 64*880 = 56320 >= 55815
#define KT 32

__global__ __launch_bounds__(256)
void fc1_kernel(const float* __restrict__ wfc) {
    __shared__ float As[128][KT + 1];
    __shared__ float Bs[128][KT + 1];

    const int m0   = blockIdx.x * 128;
    const int kb   = blockIdx.y;
    const int kbeg = kb * KCHUNK;
    const int kend = min(kbeg + KCHUNK, FC1_IN);

    const int tx = threadIdx.x & 15;
    const int ty = threadIdx.x >> 4;

    float acc[8][8];
#pragma unroll
    for (int i = 0; i < 8; i++)
#pragma unroll
        for (int j = 0; j < 8; j++) acc[i][j] = 0.f;

    for (int k0 = kbeg; k0 < kend; k0 += KT) {
        int kt = min(KT, kend - k0);
        for (int i = threadIdx.x; i < 128 * KT; i += 256) {
            int r = i >> 5, c = i & 31;
            As[r][c] = (c < kt) ? g_p2[(long)(m0 + r) * FC1_IN + k0 + c] : 0.f;
        }
        for (int i = threadIdx.x; i < 128 * KT; i += 256) {
            int r = i >> 5, c = i & 31;
            Bs[r][c] = (r < FC1_OUT && c < kt) ? wfc[(long)r * FC1_IN + k0 + c] : 0.f;
        }
        __syncthreads();
#pragma unroll
        for (int kk = 0; kk < KT; kk++) {
            float a[8], bb[8];
#pragma unroll
            for (int i = 0; i < 8; i++) a[i] = As[ty + 16 * i][kk];
#pragma unroll
            for (int j = 0; j < 8; j++) bb[j] = Bs[tx + 16 * j][kk];
#pragma unroll
            for (int i = 0; i < 8; i++)
#pragma unroll
                for (int j = 0; j < 8; j++) acc[i][j] = fmaf(a[i], bb[j], acc[i][j]);
        }
        __syncthreads();
    }
#pragma unroll
    for (int i = 0; i < 8; i++) {
        int m = m0 + ty + 16 * i;
#pragma unroll
        for (int j = 0; j < 8; j++) {
            int n = tx + 16 * j;
            if (n < FC1_OUT)
                g_fc1p[((long)kb * BATCH + m) * FC1_OUT + n] = acc[i][j];
        }
    }
}

__global__ void fc1_reduce_kernel(const float* __restrict__ bias) {
    int idx = blockIdx.x * blockDim.x + threadIdx.x;
    if (idx >= BATCH * FC1_OUT) return;
    int n = idx % FC1_OUT;
    float s = bias[n];
#pragma unroll
    for (int kb = 0; kb < KSPLIT; kb++)
        s += g_fc1p[(long)kb * BATCH * FC1_OUT + idx];
    g_h1[idx] = fmaxf(s, 0.f);
}

// ================= fc2 =================
__global__ void fc2_kernel(const float* __restrict__ w, const float* __restrict__ bias) {
    int b = blockIdx.x;
    __shared__ float h[FC1_OUT];
    if (threadIdx.x < FC1_OUT) h[threadIdx.x] = g_h1[b * FC1_OUT + threadIdx.x];
    __syncthreads();
    int n = threadIdx.x;
    if (n < FC2_OUT) {
        float s = bias[n];
        const float* wr = w + n * FC1_OUT;
#pragma unroll 8
        for (int k = 0; k < FC1_OUT; k++) s = fmaf(h[k], wr[k], s);
        g_feat[b * FC2_OUT + n] = s;
    }
}

// ================= head =================
__global__ void head_kernel(const float* __restrict__ fc3w, const float* __restrict__ fc3b,
                            const float* __restrict__ plw, const float* __restrict__ plb,
                            const float* __restrict__ pls, const float* __restrict__ plbias) {
    int b = threadIdx.x;
    float s = fc3b[0];
    float nrm = 0.f;
#pragma unroll 4
    for (int k = 0; k < FC2_OUT; k++) {
        float f = g_feat[b * FC2_OUT + k];
        s = fmaf(f, fc3w[k], s);
        nrm = fmaf(f, f, nrm);
    }
    g_norms[b] = sqrtf(nrm);
    float z = tanhf(s * plw[0] + plb[0]) * pls[0] + plbias[0];
    g_probs[b] = 1.f / (1.f + expf(-z));
}

// ================= graph aggregation =================
__global__ void graph_kernel(float* __restrict__ out) {
    int i = blockIdx.x;
    int j = threadIdx.x;
    __shared__ float fi[FC2_OUT];
    __shared__ float sdeg[256];
    __shared__ float ssum[256];
    if (j < FC2_OUT) fi[j] = g_feat[i * FC2_OUT + j];
    __syncthreads();

    float dot = 0.f;
#pragma unroll 4
    for (int k = 0; k < FC2_OUT; k++) dot = fmaf(fi[k], g_feat[j * FC2_OUT + k], dot);
    float sim = dot / (g_norms[i] * g_norms[j] + 1e-12f);
    float a = (sim >= 0.f && i != j) ? 1.f : 0.f;

    sdeg[j] = a;
    ssum[j] = a * g_probs[j];
    __syncthreads();
    for (int s = 128; s > 0; s >>= 1) {
        if (j < s) { sdeg[j] += sdeg[j + s]; ssum[j] += ssum[j + s]; }
        __syncthreads();
    }
    if (j == 0) {
        float deg = sdeg[0];
        float nm  = (deg > 0.f) ? (ssum[0] / fmaxf(deg, 1.f)) : 0.f;
        float agg = (g_probs[i] + nm) / (1.f + deg);
        out[i * 2 + 0] = agg;
        out[i * 2 + 1] = 1.f - agg;
    }
}

// ================= launch =================
extern "C" void kernel_launch(void* const* d_in, const int* in_sizes, int n_in,
                              void* d_out, int out_size) {
    const float* x       = (const float*)d_in[0];
    const float* conv1_w = (const float*)d_in[1];
    const float* conv1_b = (const float*)d_in[2];
    const float* conv2_w = (const float*)d_in[3];
    const float* conv2_b = (const float*)d_in[4];
    const float* fc1_w   = (const float*)d_in[5];
    const float* fc1_b   = (const float*)d_in[6];
    const float* fc2_w   = (const float*)d_in[7];
    const float* fc2_b   = (const float*)d_in[8];
    const float* fc3_w   = (const float*)d_in[9];
    const float* fc3_b   = (const float*)d_in[10];
    const float* pl_w    = (const float*)d_in[11];
    const float* pl_b    = (const float*)d_in[12];
    const float* pl_s    = (const float*)d_in[13];
    const float* pl_bias = (const float*)d_in[14];
    float* out = (float*)d_out;

    cudaFuncSetAttribute(conv2_pool_kernel,
                         cudaFuncAttributeMaxDynamicSharedMemorySize, C2_SMEM_BYTES);

    // conv1 + relu + pool1 (fused)
    {
        dim3 grd((P1_OH + C1_TPX - 1) / C1_TPX, (P1_OH + C1_TPY - 1) / C1_TPY, BATCH);
        conv1_pool_kernel<<<grd, C1_THREADS>>>(x, conv1_w, conv1_b);
    }
    // conv2 + relu + pool2 (fused)
    {
        dim3 grd((P2_OH + C2_TPX - 1) / C2_TPX, (P2_OH + C2_TPY - 1) / C2_TPY, BATCH);
        conv2_pool_kernel<<<grd, C2_THREADS, C2_SMEM_BYTES>>>(conv2_w, conv2_b);
    }
    // fc1 (K-split GEMM) + reduce
    {
        dim3 grd(2, KSPLIT);
        fc1_kernel<<<grd, 256>>>(fc1_w);
        fc1_reduce_kernel<<<(BATCH * FC1_OUT + 255) / 256, 256>>>(fc1_b);
    }
    fc2_kernel<<<BATCH, 128>>>(fc2_w, fc2_b);
    head_kernel<<<1, BATCH>>>(fc3_w, fc3_b, pl_w, pl_b, pl_s, pl_bias);
    graph_kernel<<<BATCH, BATCH>>>(out);
}

// round 4
// speedup vs baseline: 1.6237x; 1.3215x over previous
#include <cuda_runtime.h>
#include <math.h>

// ---------------- problem constants ----------------
#define BATCH 256
#define C1_IC 3
#define C1_OC 6
#define C1_IH 250
#define C1_OH 124
#define P1_OH 123
#define C2_IC 6
#define C2_OC 15
#define C2_OH 62
#define P2_OH 61
#define FC1_IN 55815   // 15*61*61
#define FC1_OUT 120
#define FC2_OUT 84

typedef unsigned long long ull;

// ---------------- f32x2 packed helpers ----------------
__device__ __forceinline__ ull pk2(float lo, float hi) {
    ull r; asm("mov.b64 %0, {%1,%2};" : "=l"(r) : "f"(lo), "f"(hi)); return r;
}
__device__ __forceinline__ void upk2(float& lo, float& hi, ull v) {
    asm("mov.b64 {%0,%1}, %2;" : "=f"(lo), "=f"(hi) : "l"(v));
}
__device__ __forceinline__ void fma2(ull& d, ull a, ull b) {
    asm("fma.rn.f32x2 %0, %1, %2, %3;" : "=l"(d) : "l"(a), "l"(b), "l"(d));
}

// ---------------- device scratch ----------------
__device__ float g_p1[BATCH * C1_OC * P1_OH * P1_OH];     // 93 MB
__device__ float g_p2[BATCH * C2_OC * P2_OH * P2_OH];     // 57 MB (fc1 input)
__device__ float g_fc1p[73 * BATCH * FC1_OUT];            // K-split partials
__device__ float g_h1[BATCH * FC1_OUT];
__device__ float g_feat[BATCH * FC2_OUT];
__device__ float g_probs[BATCH];

// ================= conv1 (5x5,s2,p1) + relu + maxpool(2,s1), fused, FFMA2 =================
#define C1_TPX 32
#define C1_TPY 16
#define C1_CW 33
#define C1_CH 17
#define C1_XW 69                        // (33-1)*2+5
#define C1_XWP 73                       // +4 pad for strip overreach
#define C1_XH 37                        // (17-1)*2+5
#define C1_T 128
#define C1_NP 3                         // oc pairs (6 oc)

__global__ __launch_bounds__(C1_T)
void conv1_pool_kernel(const float* __restrict__ x,
                       const float* __restrict__ w,
                       const float* __restrict__ bias) {
    __shared__ float xs[C1_IC][C1_XH][C1_XWP];        // 32.4 KB
    __shared__ float cbuf[C1_OC][C1_CH * C1_CW];      // 13.5 KB
    __shared__ __align__(16) float2 sw2[C1_IC * 25 * C1_NP];  // 1.8 KB
    __shared__ float sb[C1_OC];

    const int tid = threadIdx.x;
    const int b   = blockIdx.z;
    const int px0 = blockIdx.x * C1_TPX;
    const int py0 = blockIdx.y * C1_TPY;
    const int ix0 = px0 * 2 - 1;
    const int iy0 = py0 * 2 - 1;

    // pre-pack weights into oc-pairs: sw2[(ic*25+t)*3+q] = (w[2q][ic][t], w[2q+1][ic][t])
    for (int i = tid; i < C1_IC * 25 * C1_NP; i += C1_T) {
        int q = i % C1_NP;
        int rest = i / C1_NP;
        int ic = rest / 25, t = rest % 25;
        float w0 = w[((2 * q) * C1_IC + ic) * 25 + t];
        float w1 = w[((2 * q + 1) * C1_IC + ic) * 25 + t];
        sw2[i] = make_float2(w0, w1);
    }
    if (tid < C1_OC) sb[tid] = bias[tid];

    const float* xb = x + (long)b * C1_IC * C1_IH * C1_IH;
    for (int i = tid; i < C1_IC * C1_XH * C1_XW; i += C1_T) {
        int ic = i / (C1_XH * C1_XW);
        int r  = (i / C1_XW) % C1_XH;
        int c  = i % C1_XW;
        int iy = iy0 + r, ix = ix0 + c;
        float v = 0.f;
        if (iy >= 0 && iy < C1_IH && ix >= 0 && ix < C1_IH)
            v = xb[ic * C1_IH * C1_IH + iy * C1_IH + ix];
        xs[ic][r][c] = v;
    }
    __syncthreads();

    // row-strip: thread owns conv row (tid/7), cols cx0..cx0+4
    const int row = tid / 7;
    const int cx0 = (tid % 7) * 5;
    if (row < C1_CH) {
        ull acc[5][C1_NP];
#pragma unroll
        for (int u = 0; u < 5; u++)
#pragma unroll
            for (int q = 0; q < C1_NP; q++) acc[u][q] = 0ull;

#pragma unroll 1
        for (int ic = 0; ic < C1_IC; ic++) {
#pragma unroll 1
            for (int ky = 0; ky < 5; ky++) {
                const float* xr = &xs[ic][row * 2 + ky][cx0 * 2];
                ull xx[13];
#pragma unroll
                for (int o = 0; o < 13; o++) { float v = xr[o]; xx[o] = pk2(v, v); }
                const float2* wp = &sw2[(ic * 25 + ky * 5) * C1_NP];
#pragma unroll
                for (int kx = 0; kx < 5; kx++) {
                    ull w2[C1_NP];
#pragma unroll
                    for (int q = 0; q < C1_NP; q++)
                        w2[q] = *(const ull*)&wp[kx * C1_NP + q];
#pragma unroll
                    for (int u = 0; u < 5; u++)
#pragma unroll
                        for (int q = 0; q < C1_NP; q++)
                            fma2(acc[u][q], xx[2 * u + kx], w2[q]);
                }
            }
        }
#pragma unroll
        for (int u = 0; u < 5; u++) {
            int cx = cx0 + u;
            if (cx < C1_CW) {
#pragma unroll
                for (int q = 0; q < C1_NP; q++) {
                    float lo, hi; upk2(lo, hi, acc[u][q]);
                    cbuf[2 * q][row * C1_CW + cx]     = fmaxf(lo + sb[2 * q], 0.f);
                    cbuf[2 * q + 1][row * C1_CW + cx] = fmaxf(hi + sb[2 * q + 1], 0.f);
                }
            }
        }
    }
    __syncthreads();

    for (int m = tid; m < C1_OC * C1_TPY * C1_TPX; m += C1_T) {
        int oc  = m / (C1_TPY * C1_TPX);
        int rem = m % (C1_TPY * C1_TPX);
        int pyl = rem / C1_TPX, pxl = rem % C1_TPX;
        int px = px0 + pxl, py = py0 + pyl;
        if (px < P1_OH && py < P1_OH) {
            const float* cb = &cbuf[oc][pyl * C1_CW + pxl];
            float v = fmaxf(fmaxf(cb[0], cb[1]), fmaxf(cb[C1_CW], cb[C1_CW + 1]));
            g_p1[((long)(b * C1_OC + oc) * P1_OH + py) * P1_OH + px] = v;
        }
    }
}

// ================= conv2 (3x3,s2,p1) + relu + maxpool(2,s1), fused, FFMA2 =================
#define C2_TPX 32
#define C2_TPY 16
#define C2_CW 33
#define C2_CH 17
#define C2_XW 67                       // (33-1)*2+3
#define C2_XWP 71                      // +4 pad
#define C2_XH 35                       // (17-1)*2+3
#define C2_T 128
#define C2_NP 8                        // oc pairs (15 oc padded to 16)
#define C2_XS_SZ (C2_IC * C2_XH * C2_XWP)              // 14910 floats (even)
#define C2_CB_SZ 8416                                  // 15*17*33=8415, padded EVEN for 8B alignment
#define C2_SW_SZ (C2_IC * 9 * C2_NP)                   // 432 float2
#define C2_SMEM_BYTES (C2_XS_SZ * 4 + C2_CB_SZ * 4 + C2_SW_SZ * 8 + 64)

__global__ __launch_bounds__(C2_T)
void conv2_pool_kernel(const float* __restrict__ w,
                       const float* __restrict__ bias) {
    extern __shared__ __align__(16) float smem[];
    float*  xs   = smem;                                // [ic][XH][XWP]
    float*  cbuf = xs + C2_XS_SZ;                       // [oc][CH*CW]
    float2* sw2  = (float2*)(cbuf + C2_CB_SZ);          // 8B-aligned: (14910+8416)*4 % 8 == 0
    float*  sb   = (float*)(sw2 + C2_SW_SZ);

    const int tid = threadIdx.x;
    const int b   = blockIdx.z;
    const int px0 = blockIdx.x * C2_TPX;
    const int py0 = blockIdx.y * C2_TPY;
    const int ix0 = px0 * 2 - 1;
    const int iy0 = py0 * 2 - 1;

    for (int i = tid; i < C2_SW_SZ; i += C2_T) {
        int q = i % C2_NP;
        int rest = i / C2_NP;
        int ic = rest / 9, t = rest % 9;
        int oc0 = 2 * q, oc1 = 2 * q + 1;
        float w0 = (oc0 < C2_OC) ? w[(oc0 * C2_IC + ic) * 9 + t] : 0.f;
        float w1 = (oc1 < C2_OC) ? w[(oc1 * C2_IC + ic) * 9 + t] : 0.f;
        sw2[i] = make_float2(w0, w1);
    }
    if (tid < C2_OC) sb[tid] = bias[tid];

    const float* xb = g_p1 + (long)b * C2_IC * P1_OH * P1_OH;
    for (int i = tid; i < C2_IC * C2_XH * C2_XW; i += C2_T) {
        int ic = i / (C2_XH * C2_XW);
        int r  = (i / C2_XW) % C2_XH;
        int c  = i % C2_XW;
        int iy = iy0 + r, ix = ix0 + c;
        float v = 0.f;
        if (iy >= 0 && iy < P1_OH && ix >= 0 && ix < P1_OH)
            v = xb[ic * P1_OH * P1_OH + iy * P1_OH + ix];
        xs[(ic * C2_XH + r) * C2_XWP + c] = v;
    }
    __syncthreads();

    const int row = tid / 7;
    const int cx0 = (tid % 7) * 5;
    if (row < C2_CH) {
        ull acc[5][C2_NP];
#pragma unroll
        for (int u = 0; u < 5; u++)
#pragma unroll
            for (int q = 0; q < C2_NP; q++) acc[u][q] = 0ull;

#pragma unroll 1
        for (int ic = 0; ic < C2_IC; ic++) {
#pragma unroll 1
            for (int ky = 0; ky < 3; ky++) {
                const float* xr = &xs[(ic * C2_XH + row * 2 + ky) * C2_XWP + cx0 * 2];
                ull xx[11];
#pragma unroll
                for (int o = 0; o < 11; o++) { float v = xr[o]; xx[o] = pk2(v, v); }
                const float2* wp = &sw2[(ic * 9 + ky * 3) * C2_NP];
#pragma unroll
                for (int kx = 0; kx < 3; kx++) {
                    ull w2[C2_NP];
#pragma unroll
                    for (int q = 0; q < C2_NP; q++)
                        w2[q] = *(const ull*)&wp[kx * C2_NP + q];
#pragma unroll
                    for (int u = 0; u < 5; u++)
#pragma unroll
                        for (int q = 0; q < C2_NP; q++)
                            fma2(acc[u][q], xx[2 * u + kx], w2[q]);
                }
            }
        }
#pragma unroll
        for (int u = 0; u < 5; u++) {
            int cx = cx0 + u;
            if (cx < C2_CW) {
#pragma unroll
                for (int q = 0; q < C2_NP; q++) {
                    float lo, hi; upk2(lo, hi, acc[u][q]);
                    int oc0 = 2 * q, oc1 = 2 * q + 1;
                    cbuf[oc0 * (C2_CH * C2_CW) + row * C2_CW + cx] = fmaxf(lo + sb[oc0], 0.f);
                    if (oc1 < C2_OC)
                        cbuf[oc1 * (C2_CH * C2_CW) + row * C2_CW + cx] = fmaxf(hi + sb[oc1], 0.f);
                }
            }
        }
    }
    __syncthreads();

    for (int m = tid; m < C2_OC * C2_TPY * C2_TPX; m += C2_T) {
        int oc  = m / (C2_TPY * C2_TPX);
        int rem = m % (C2_TPY * C2_TPX);
        int pyl = rem / C2_TPX, pxl = rem % C2_TPX;
        int px = px0 + pxl, py = py0 + pyl;
        if (px < P2_OH && py < P2_OH) {
            const float* cb = &cbuf[oc * (C2_CH * C2_CW) + pyl * C2_CW + pxl];
            float v = fmaxf(fmaxf(cb[0], cb[1]), fmaxf(cb[C2_CW], cb[C2_CW + 1]));
            g_p2[((long)(b * C2_OC + oc) * P2_OH + py) * P2_OH + px] = v;
        }
    }
}

// ================= fc1: [256,55815] @ [120,55815]^T, K-split, FFMA2, reg-prefetch ==========
#define KSPLIT 73
#define KCHUNK 768     // 73*768 = 56064 >= 55815
#define KT 32
#define BSROW 130      // EVEN padded floats per kk row (row stride 520B ≡ 0 mod 8)

__global__ __launch_bounds__(256)
void fc1_kernel(const float* __restrict__ wfc) {
    __shared__ float As[128][KT + 1];                  // [m][kk]
    __shared__ __align__(16) float Bs[KT][BSROW];      // [kk][n], base 16B-aligned for ull loads

    const int m0   = blockIdx.x * 128;
    const int kb   = blockIdx.y;
    const int tid  = threadIdx.x;
    const int tx   = tid & 15;
    const int ty   = tid >> 4;

    ull acc[8][4];
#pragma unroll
    for (int i = 0; i < 8; i++)
#pragma unroll
        for (int q = 0; q < 4; q++) acc[i][q] = 0ull;

    float rA[16], rB[16];
    int k0 = kb * KCHUNK;
#pragma unroll
    for (int t = 0; t < 16; t++) {
        int i = t * 256 + tid;
        int r = i >> 5, c = i & 31;
        int k = k0 + c;
        rA[t] = (k < FC1_IN) ? g_p2[(long)(m0 + r) * FC1_IN + k] : 0.f;
        rB[t] = (r < FC1_OUT && k < FC1_IN) ? wfc[(long)r * FC1_IN + k] : 0.f;
    }

#pragma unroll 1
    for (int step = 0; step < KCHUNK / KT; step++) {
#pragma unroll
        for (int t = 0; t < 16; t++) {
            int i = t * 256 + tid;
            int r = i >> 5, c = i & 31;
            As[r][c] = rA[t];
            Bs[c][r] = rB[t];
        }
        __syncthreads();

        int k1 = k0 + KT;
        if (step + 1 < KCHUNK / KT) {
#pragma unroll
            for (int t = 0; t < 16; t++) {
                int i = t * 256 + tid;
                int r = i >> 5, c = i & 31;
                int k = k1 + c;
                rA[t] = (k < FC1_IN) ? g_p2[(long)(m0 + r) * FC1_IN + k] : 0.f;
                rB[t] = (r < FC1_OUT && k < FC1_IN) ? wfc[(long)r * FC1_IN + k] : 0.f;
            }
        }

#pragma unroll 4
        for (int kk = 0; kk < KT; kk++) {
            ull b2[4], a2[8];
            const ull* bp = (const ull*)&Bs[kk][0];
#pragma unroll
            for (int q = 0; q < 4; q++) b2[q] = bp[tx + 16 * q];
#pragma unroll
            for (int i = 0; i < 8; i++) { float av = As[ty + 16 * i][kk]; a2[i] = pk2(av, av); }
#pragma unroll
            for (int i = 0; i < 8; i++)
#pragma unroll
                for (int q = 0; q < 4; q++) fma2(acc[i][q], a2[i], b2[q]);
        }
        k0 = k1;
        __syncthreads();
    }

#pragma unroll
    for (int i = 0; i < 8; i++) {
        int m = m0 + ty + 16 * i;
#pragma unroll
        for (int q = 0; q < 4; q++) {
            float lo, hi; upk2(lo, hi, acc[i][q]);
            int n = 2 * (tx + 16 * q);
            if (n < FC1_OUT)     g_fc1p[((long)kb * BATCH + m) * FC1_OUT + n]     = lo;
            if (n + 1 < FC1_OUT) g_fc1p[((long)kb * BATCH + m) * FC1_OUT + n + 1] = hi;
        }
    }
}

__global__ void fc1_reduce_kernel(const float* __restrict__ bias) {
    int idx = blockIdx.x * blockDim.x + threadIdx.x;
    if (idx >= BATCH * FC1_OUT) return;
    int n = idx % FC1_OUT;
    float s = bias[n];
#pragma unroll
    for (int kb = 0; kb < KSPLIT; kb++)
        s += g_fc1p[(long)kb * BATCH * FC1_OUT + idx];
    g_h1[idx] = fmaxf(s, 0.f);
}

// ================= fc2 + head fused =================
__global__ __launch_bounds__(128)
void fc2_head_kernel(const float* __restrict__ w, const float* __restrict__ bias,
                     const float* __restrict__ fc3w, const float* __restrict__ fc3b,
                     const float* __restrict__ plw, const float* __restrict__ plb,
                     const float* __restrict__ pls, const float* __restrict__ plbias) {
    int b = blockIdx.x;
    int tid = threadIdx.x;
    __shared__ float h[FC1_OUT];
    __shared__ float fs[FC2_OUT];
    __shared__ float wsum[4];

    if (tid < FC1_OUT) h[tid] = g_h1[b * FC1_OUT + tid];
    __syncthreads();
    if (tid < FC2_OUT) {
        float s = bias[tid];
        const float* wr = w + tid * FC1_OUT;
#pragma unroll 8
        for (int k = 0; k < FC1_OUT; k++) s = fmaf(h[k], wr[k], s);
        fs[tid] = s;
        g_feat[b * FC2_OUT + tid] = s;
    }
    __syncthreads();

    float p = (tid < FC2_OUT) ? fs[tid] * fc3w[tid] : 0.f;
#pragma unroll
    for (int o = 16; o > 0; o >>= 1) p += __shfl_xor_sync(0xffffffff, p, o);
    if ((tid & 31) == 0) wsum[tid >> 5] = p;
    __syncthreads();
    if (tid == 0) {
        float s = wsum[0] + wsum[1] + wsum[2] + wsum[3] + fc3b[0];
        float z = tanhf(s * plw[0] + plb[0]) * pls[0] + plbias[0];
        g_probs[b] = 1.f / (1.f + expf(-z));
    }
}

// ================= graph aggregation (sign(dot) == sign(sim), THRESH=0) =================
__global__ void graph_kernel(float* __restrict__ out) {
    int i = blockIdx.x;
    int j = threadIdx.x;
    __shared__ float fi[FC2_OUT];
    __shared__ float sdeg[256];
    __shared__ float ssum[256];
    if (j < FC2_OUT) fi[j] = g_feat[i * FC2_OUT + j];
    __syncthreads();

    float dot = 0.f;
#pragma unroll 4
    for (int k = 0; k < FC2_OUT; k++) dot = fmaf(fi[k], g_feat[j * FC2_OUT + k], dot);
    float a = (dot >= 0.f && i != j) ? 1.f : 0.f;

    sdeg[j] = a;
    ssum[j] = a * g_probs[j];
    __syncthreads();
    for (int s = 128; s > 0; s >>= 1) {
        if (j < s) { sdeg[j] += sdeg[j + s]; ssum[j] += ssum[j + s]; }
        __syncthreads();
    }
    if (j == 0) {
        float deg = sdeg[0];
        float nm  = (deg > 0.f) ? (ssum[0] / fmaxf(deg, 1.f)) : 0.f;
        float agg = (g_probs[i] + nm) / (1.f + deg);
        out[i * 2 + 0] = agg;
        out[i * 2 + 1] = 1.f - agg;
    }
}

// ================= launch =================
extern "C" void kernel_launch(void* const* d_in, const int* in_sizes, int n_in,
                              void* d_out, int out_size) {
    const float* x       = (const float*)d_in[0];
    const float* conv1_w = (const float*)d_in[1];
    const float* conv1_b = (const float*)d_in[2];
    const float* conv2_w = (const float*)d_in[3];
    const float* conv2_b = (const float*)d_in[4];
    const float* fc1_w   = (const float*)d_in[5];
    const float* fc1_b   = (const float*)d_in[6];
    const float* fc2_w   = (const float*)d_in[7];
    const float* fc2_b   = (const float*)d_in[8];
    const float* fc3_w   = (const float*)d_in[9];
    const float* fc3_b   = (const float*)d_in[10];
    const float* pl_w    = (const float*)d_in[11];
    const float* pl_b    = (const float*)d_in[12];
    const float* pl_s    = (const float*)d_in[13];
    const float* pl_bias = (const float*)d_in[14];
    float* out = (float*)d_out;

    cudaFuncSetAttribute(conv2_pool_kernel,
                         cudaFuncAttributeMaxDynamicSharedMemorySize, C2_SMEM_BYTES);

    {
        dim3 grd((P1_OH + C1_TPX - 1) / C1_TPX, (P1_OH + C1_TPY - 1) / C1_TPY, BATCH);
        conv1_pool_kernel<<<grd, C1_T>>>(x, conv1_w, conv1_b);
    }
    {
        dim3 grd((P2_OH + C2_TPX - 1) / C2_TPX, (P2_OH + C2_TPY - 1) / C2_TPY, BATCH);
        conv2_pool_kernel<<<grd, C2_T, C2_SMEM_BYTES>>>(conv2_w, conv2_b);
    }
    {
        dim3 grd(2, KSPLIT);
        fc1_kernel<<<grd, 256>>>(fc1_w);
        fc1_reduce_kernel<<<(BATCH * FC1_OUT + 127) / 128, 128>>>(fc1_b);
    }
    fc2_head_kernel<<<BATCH, 128>>>(fc2_w, fc2_b, fc3_w, fc3_b, pl_w, pl_b, pl_s, pl_bias);
    graph_kernel<<<BATCH, BATCH>>>(out);
}